// round 1
// baseline (speedup 1.0000x reference)
#include <cuda_runtime.h>
#include <cuda_bf16.h>

// Problem constants (shapes are static: feature maps only contribute H,W).
#define NB 16          // batch
#define NM 64          // gt boxes per image
#define A_TOTAL 48960  // (64*64 + 32*32 + 16*16 + 8*8) * 9

// Level offsets (anchors per level = H*W*9)
// L3: [0, 36864)      H=W=64, stride 8,  size 32
// L4: [36864, 46080)  H=W=32, stride 16, size 64
// L5: [46080, 48384)  H=W=16, stride 32, size 128
// L6: [48384, 48960)  H=W=8,  stride 64, size 256

__global__ void anchors_assign_kernel(const float* __restrict__ gt_boxes,
                                      const int*   __restrict__ gt_labels_raw,
                                      float*       __restrict__ out)
{
    __shared__ float4 s_box[NM];
    __shared__ float  s_area[NM];
    __shared__ int    s_lab[NM];

    const int b   = blockIdx.y;
    const int tid = threadIdx.x;
    const int a   = blockIdx.x * blockDim.x + tid;

    if (tid < NM) {
        const float4 g = ((const float4*)(gt_boxes + (size_t)b * NM * 4))[tid];
        s_box[tid]  = g;
        s_area[tid] = (g.z - g.x) * (g.w - g.y);
        // dtype probe: labels are in [1,21), so int64 layout has zero high words.
        bool is64 = (gt_labels_raw[1] == 0) && (gt_labels_raw[3] == 0) &&
                    (gt_labels_raw[5] == 0);
        int idx = b * NM + tid;
        s_lab[tid] = is64 ? gt_labels_raw[2 * idx] : gt_labels_raw[idx];
    }
    __syncthreads();

    if (a >= A_TOTAL) return;

    // ---- decode anchor a -> (cx, cy, w, h) ----
    int i, Wd;
    float stride, bsize;
    if (a < 36864)      { i = a;         Wd = 64; stride = 8.f;  bsize = 32.f;  }
    else if (a < 46080) { i = a - 36864; Wd = 32; stride = 16.f; bsize = 64.f;  }
    else if (a < 48384) { i = a - 46080; Wd = 16; stride = 32.f; bsize = 128.f; }
    else                { i = a - 48384; Wd = 8;  stride = 64.f; bsize = 256.f; }

    const int k  = i % 9;
    const int xy = i / 9;
    const int x  = xy % Wd;
    const int y  = xy / Wd;

    const float cx = (x + 0.5f) * stride;
    const float cy = (y + 0.5f) * stride;

    const int kr = k / 3;   // ratio index: 0.5, 1.0, 2.0
    const int ks = k - kr * 3;  // scale index
    const float sqrt_r = (kr == 0) ? 0.70710678118654752f
                       : (kr == 1) ? 1.0f : 1.41421356237309505f;
    const float scl    = (ks == 0) ? 1.0f
                       : (ks == 1) ? 1.2599210498948732f : 1.5874010519681994f;
    const float aw = bsize * scl * sqrt_r;
    const float ah = bsize * scl / sqrt_r;

    const float ax0 = cx - aw * 0.5f, ay0 = cy - ah * 0.5f;
    const float ax1 = cx + aw * 0.5f, ay1 = cy + ah * 0.5f;
    const float area_a = (ax1 - ax0) * (ay1 - ay0);

    // ---- IoU max/argmax over 64 gt boxes (first-max semantics) ----
    float best = -1.0f;
    int   bidx = 0;
    #pragma unroll 8
    for (int j = 0; j < NM; ++j) {
        const float4 g = s_box[j];
        const float iw = fminf(ax1, g.z) - fmaxf(ax0, g.x);
        const float ih = fminf(ay1, g.w) - fmaxf(ay0, g.y);
        const float inter = fmaxf(iw, 0.0f) * fmaxf(ih, 0.0f);
        const float iou = inter / (area_a + s_area[j] - inter);
        if (iou > best) { best = iou; bidx = j; }
    }

    // ---- label ----
    int lab = s_lab[bidx];
    if (best > 0.4f && best < 0.5f) lab = -1;  // ignore band
    if (best < 0.4f)                lab = 0;   // background

    // ---- loc deltas vs matched box ----
    const float4 g = s_box[bidx];
    const float bw  = g.z - g.x;
    const float bh  = g.w - g.y;
    const float bcx = (g.x + g.z) * 0.5f;
    const float bcy = (g.y + g.w) * 0.5f;

    float4 d;
    d.x = (bcx - cx) / (aw * 0.1f);
    d.y = (bcy - cy) / (ah * 0.1f);
    d.z = logf(bw / aw) / 0.2f;
    d.w = logf(bh / ah) / 0.2f;

    // ---- write: loc_targets (B,A,4) then cls_targets (B,A), both as float ----
    ((float4*)out)[(size_t)b * A_TOTAL + a] = d;
    out[(size_t)NB * A_TOTAL * 4 + (size_t)b * A_TOTAL + a] = (float)lab;
}

extern "C" void kernel_launch(void* const* d_in, const int* in_sizes, int n_in,
                              void* d_out, int out_size)
{
    // inputs: f3, f4, f5, f6 (unused: shapes static), gt_boxes, gt_labels
    const float* gt_boxes  = (const float*)d_in[4];
    const int*   gt_labels = (const int*)d_in[5];
    float*       out       = (float*)d_out;

    dim3 block(256);
    dim3 grid((A_TOTAL + 255) / 256, NB);
    anchors_assign_kernel<<<grid, block>>>(gt_boxes, gt_labels, out);
}

// round 2
// speedup vs baseline: 2.4824x; 2.4824x over previous
#include <cuda_runtime.h>
#include <cuda_bf16.h>

// Problem constants (shapes are static: feature maps only contribute H,W).
#define NB 16          // batch
#define NM 64          // gt boxes per image
#define A_TOTAL 48960  // (64*64 + 32*32 + 16*16 + 8*8) * 9

__global__ void anchors_assign_kernel(const float* __restrict__ gt_boxes,
                                      const int*   __restrict__ gt_labels_raw,
                                      float*       __restrict__ out)
{
    __shared__ float4 s_box[NM];
    __shared__ float  s_area[NM];
    __shared__ int    s_lab[NM];

    const int b   = blockIdx.y;
    const int tid = threadIdx.x;
    const int a   = blockIdx.x * blockDim.x + tid;

    if (tid < NM) {
        const float4 g = ((const float4*)(gt_boxes + (size_t)b * NM * 4))[tid];
        s_box[tid]  = g;
        s_area[tid] = (g.z - g.x) * (g.w - g.y);
        // dtype probe: labels are in [1,21), so int64 layout has zero high words.
        bool is64 = (gt_labels_raw[1] == 0) && (gt_labels_raw[3] == 0) &&
                    (gt_labels_raw[5] == 0);
        int idx = b * NM + tid;
        s_lab[tid] = is64 ? gt_labels_raw[2 * idx] : gt_labels_raw[idx];
    }
    __syncthreads();

    if (a >= A_TOTAL) return;

    // ---- decode anchor a -> (cx, cy, w, h) ----
    int i, Wd;
    float stride, bsize;
    if (a < 36864)      { i = a;         Wd = 64; stride = 8.f;  bsize = 32.f;  }
    else if (a < 46080) { i = a - 36864; Wd = 32; stride = 16.f; bsize = 64.f;  }
    else if (a < 48384) { i = a - 46080; Wd = 16; stride = 32.f; bsize = 128.f; }
    else                { i = a - 48384; Wd = 8;  stride = 64.f; bsize = 256.f; }

    const int k  = i % 9;
    const int xy = i / 9;
    const int x  = xy % Wd;
    const int y  = xy / Wd;

    const float cx = (x + 0.5f) * stride;
    const float cy = (y + 0.5f) * stride;

    const int kr = k / 3;       // ratio index: 0.5, 1.0, 2.0
    const int ks = k - kr * 3;  // scale index
    const float sqrt_r = (kr == 0) ? 0.70710678118654752f
                       : (kr == 1) ? 1.0f : 1.41421356237309505f;
    const float scl    = (ks == 0) ? 1.0f
                       : (ks == 1) ? 1.2599210498948732f : 1.5874010519681994f;
    const float aw = bsize * scl * sqrt_r;
    const float ah = bsize * scl / sqrt_r;

    const float ax0 = cx - aw * 0.5f, ay0 = cy - ah * 0.5f;
    const float ax1 = cx + aw * 0.5f, ay1 = cy + ah * 0.5f;
    const float area_a = (ax1 - ax0) * (ay1 - ay0);

    // ---- IoU max/argmax over 64 gt boxes, division-free (cross-mult compare).
    // iou_j > iou_b  <=>  inter_j * U_b > inter_b * U_j   (U > 0 always).
    // Init (inter_b, U_b) = (-1, 1): j=0 always wins first -> first-max
    // semantics identical to jnp.argmax (incl. all-zero-IoU -> idx 0).
    float inter_b = -1.0f;
    float U_b     = 1.0f;
    int   bidx    = 0;
    #pragma unroll 16
    for (int j = 0; j < NM; ++j) {
        const float4 g = s_box[j];
        const float iw = fminf(ax1, g.z) - fmaxf(ax0, g.x);
        const float ih = fminf(ay1, g.w) - fmaxf(ay0, g.y);
        const float inter = fmaxf(iw, 0.0f) * fmaxf(ih, 0.0f);
        const float U = (area_a + s_area[j]) - inter;
        const bool upd = inter * U_b > inter_b * U;
        inter_b = upd ? inter : inter_b;
        U_b     = upd ? U     : U_b;
        bidx    = upd ? j     : bidx;
    }

    const float best = inter_b / U_b;  // one real division per thread

    // ---- label ----
    int lab = s_lab[bidx];
    if (best > 0.4f && best < 0.5f) lab = -1;  // ignore band
    if (best < 0.4f)                lab = 0;   // background

    // ---- loc deltas vs matched box ----
    const float4 g = s_box[bidx];
    const float bw  = g.z - g.x;
    const float bh  = g.w - g.y;
    const float bcx = (g.x + g.z) * 0.5f;
    const float bcy = (g.y + g.w) * 0.5f;

    float4 d;
    d.x = (bcx - cx) / (aw * 0.1f);
    d.y = (bcy - cy) / (ah * 0.1f);
    d.z = __logf(bw / aw) * 5.0f;   // 1/0.2
    d.w = __logf(bh / ah) * 5.0f;

    // ---- write: loc_targets (B,A,4) then cls_targets (B,A), both as float ----
    ((float4*)out)[(size_t)b * A_TOTAL + a] = d;
    out[(size_t)NB * A_TOTAL * 4 + (size_t)b * A_TOTAL + a] = (float)lab;
}

extern "C" void kernel_launch(void* const* d_in, const int* in_sizes, int n_in,
                              void* d_out, int out_size)
{
    // inputs: f3, f4, f5, f6 (unused: shapes static), gt_boxes, gt_labels
    const float* gt_boxes  = (const float*)d_in[4];
    const int*   gt_labels = (const int*)d_in[5];
    float*       out       = (float*)d_out;

    dim3 block(256);
    dim3 grid((A_TOTAL + 255) / 256, NB);
    anchors_assign_kernel<<<grid, block>>>(gt_boxes, gt_labels, out);
}

// round 4
// speedup vs baseline: 3.4440x; 1.3873x over previous
#include <cuda_runtime.h>
#include <cuda_bf16.h>

#define NB 16          // batch
#define NM 64          // gt boxes per image
#define A_TOTAL 48960
#define NK 9
#define XT 8
#define YT 8
#define NTHREADS (XT * YT * NK)   // 576

__global__ __launch_bounds__(NTHREADS, 3)
void anchors_assign_kernel(const float* __restrict__ gt_boxes,
                           const int*   __restrict__ gt_labels_raw,
                           float*       __restrict__ out)
{
    __shared__ float4 s_box[NM];
    __shared__ float  s_area[NM];
    __shared__ int    s_lab[NM];
    __shared__ float  s_rAS[NM][NK];        // 1/(area_a[k] + area_g[j])
    __shared__ float  s_IWn[NM][NK][XT];    // clamp(IW) * rAS
    __shared__ float  s_IH [NM][NK][YT];    // clamp(IH)

    const int b   = blockIdx.y;
    const int tid = threadIdx.x;

    // ---- decode tile: (level, x0, y0) from blockIdx.x in [0,85) ----
    int t = blockIdx.x;
    int x0, y0, base, W;
    float stride, bsize;
    if (t < 64)      { x0 = (t & 7) * 8;        y0 = (t >> 3) * 8;        base = 0;     W = 64; stride = 8.f;  bsize = 32.f;  }
    else if (t < 80) { int u = t - 64; x0 = (u & 3) * 8; y0 = (u >> 2) * 8; base = 36864; W = 32; stride = 16.f; bsize = 64.f;  }
    else if (t < 84) { int u = t - 80; x0 = (u & 1) * 8; y0 = (u >> 1) * 8; base = 46080; W = 16; stride = 32.f; bsize = 128.f; }
    else             { x0 = 0;                  y0 = 0;                    base = 48384; W = 8;  stride = 64.f; bsize = 256.f; }

    // ---- phase 1: boxes, areas, labels ----
    if (tid < NM) {
        const float4 g = ((const float4*)(gt_boxes + (size_t)b * NM * 4))[tid];
        s_box[tid]  = g;
        s_area[tid] = (g.z - g.x) * (g.w - g.y);
        // dtype probe: labels in [1,21), int64 layout has zero high words.
        bool is64 = (gt_labels_raw[1] == 0) && (gt_labels_raw[3] == 0) &&
                    (gt_labels_raw[5] == 0);
        int idx = b * NM + tid;
        s_lab[tid] = is64 ? gt_labels_raw[2 * idx] : gt_labels_raw[idx];
    }
    __syncthreads();

    // ---- phase 2a: rAS[j][k] = 1/(area_a + area_g), one entry per thread ----
    {
        const int j = tid & 63;
        const int k = tid >> 6;                  // 0..8
        const int ks = k % 3;                    // scale index
        const float scl2 = (ks == 0) ? 1.0f
                         : (ks == 1) ? 1.5874010519681994f   // 2^(2/3)
                                     : 2.5198420997897464f;  // 2^(4/3)
        const float area_a = bsize * bsize * scl2;           // aw*ah = bsize^2*scl^2
        s_rAS[j][k] = 1.0f / (area_a + s_area[j]);
    }
    __syncthreads();

    // ---- phase 2b: build IWn and IH tables (8 entries each per thread) ----
    #pragma unroll
    for (int it = 0; it < 8; ++it) {
        const int e  = tid + NTHREADS * it;      // 0..4607
        const int x  = e & 7;
        const int kk = (e >> 3) % 9;
        const int j  = e / 72;
        const int kr = kk / 3, ks = kk % 3;
        const float sr  = (kr == 0) ? 0.70710678118654752f
                        : (kr == 1) ? 1.0f : 1.41421356237309505f;
        const float scl = (ks == 0) ? 1.0f
                        : (ks == 1) ? 1.2599210498948732f : 1.5874010519681994f;
        const float hw = 0.5f * bsize * scl * sr;
        const float cx = (x0 + x + 0.5f) * stride;
        const float4 g = s_box[j];
        const float iw = fminf(cx + hw, g.z) - fmaxf(cx - hw, g.x);
        s_IWn[j][kk][x] = fmaxf(iw, 0.0f) * s_rAS[j][kk];

        const float hh = 0.5f * bsize * scl / sr;
        const float cy = (y0 + x + 0.5f) * stride;   // reuse e-decode: x plays "y"
        const float ih = fminf(cy + hh, g.w) - fmaxf(cy - hh, g.y);
        s_IH[j][kk][x] = fmaxf(ih, 0.0f);
    }
    __syncthreads();

    // ---- main: per-anchor argmax of s_j = IWn * IH (monotone in IoU) ----
    const int k = tid >> 6;        // anchor shape
    const int r = tid & 63;
    const int x = r & 7;
    const int y = r >> 3;

    const float* __restrict__ pw = &s_IWn[0][k][x];   // stride 72 floats over j
    const float* __restrict__ ph = &s_IH[0][k][y];

    float best_s = 0.0f;           // s >= 0; strict > gives first-max (all-zero -> 0)
    int   bidx   = 0;
    #pragma unroll 8
    for (int j = 0; j < NM; ++j) {
        const float s = pw[j * (NK * XT)] * ph[j * (NK * YT)];
        if (s > best_s) { best_s = s; bidx = j; }
    }

    // ---- epilogue: exact IoU for the winner, label, deltas ----
    const int kr = k / 3, ks = k % 3;
    const float sr  = (kr == 0) ? 0.70710678118654752f
                    : (kr == 1) ? 1.0f : 1.41421356237309505f;
    const float scl = (ks == 0) ? 1.0f
                    : (ks == 1) ? 1.2599210498948732f : 1.5874010519681994f;
    const float aw = bsize * scl * sr;
    const float ah = bsize * scl / sr;
    const float cx = (x0 + x + 0.5f) * stride;
    const float cy = (y0 + y + 0.5f) * stride;

    const float4 g = s_box[bidx];
    const float iw = fminf(cx + 0.5f * aw, g.z) - fmaxf(cx - 0.5f * aw, g.x);
    const float ih = fminf(cy + 0.5f * ah, g.w) - fmaxf(cy - 0.5f * ah, g.y);
    const float inter = fmaxf(iw, 0.0f) * fmaxf(ih, 0.0f);
    const float U = (aw * ah + s_area[bidx]) - inter;
    const float best = inter / U;                 // exact div for thresholds

    int lab = s_lab[bidx];
    if (best > 0.4f && best < 0.5f) lab = -1;
    if (best < 0.4f)                lab = 0;

    const float bw  = g.z - g.x;
    const float bh  = g.w - g.y;
    const float bcx = (g.x + g.z) * 0.5f;
    const float bcy = (g.y + g.w) * 0.5f;

    float4 d;
    d.x = __fdividef(bcx - cx, 0.1f * aw);
    d.y = __fdividef(bcy - cy, 0.1f * ah);
    d.z = __logf(__fdividef(bw, aw)) * 5.0f;
    d.w = __logf(__fdividef(bh, ah)) * 5.0f;

    const int a = base + (((y0 + y) * W + (x0 + x)) * NK + k);
    ((float4*)out)[(size_t)b * A_TOTAL + a] = d;
    out[(size_t)NB * A_TOTAL * 4 + (size_t)b * A_TOTAL + a] = (float)lab;
}

extern "C" void kernel_launch(void* const* d_in, const int* in_sizes, int n_in,
                              void* d_out, int out_size)
{
    // inputs: f3, f4, f5, f6 (unused: shapes static), gt_boxes, gt_labels
    const float* gt_boxes  = (const float*)d_in[4];
    const int*   gt_labels = (const int*)d_in[5];
    float*       out       = (float*)d_out;

    dim3 block(NTHREADS);
    dim3 grid(85, NB);   // 64+16+4+1 tiles per batch
    anchors_assign_kernel<<<grid, block>>>(gt_boxes, gt_labels, out);
}

// round 6
// speedup vs baseline: 4.3399x; 1.2601x over previous
#include <cuda_runtime.h>
#include <cuda_bf16.h>

#define NB 16          // batch
#define NM 64          // gt boxes per image
#define A_TOTAL 48960
#define NK 9
#define JP 68          // padded j-stride for tables (conflict-free float4 reads)
#define NTHREADS 576

__global__ __launch_bounds__(NTHREADS, 3)
void anchors_assign_kernel(const float* __restrict__ gt_boxes,
                           const int*   __restrict__ gt_labels_raw,
                           float*       __restrict__ out)
{
    __shared__ float4 s_box[NM];
    __shared__ float  s_area[NM];
    __shared__ int    s_lab[NM];
    __shared__ int    s_cidx[NM];          // compacted -> original j
    __shared__ unsigned s_mask[2];
    __shared__ int    s_nc;
    __shared__ float  s_rAS[NM * NK];      // 1/(area_a[k] + area_g[jc])
    __shared__ __align__(16) float s_IWn[NK * 8 * JP];  // [k][x][jc]
    __shared__ __align__(16) float s_IH [NK * 8 * JP];  // [k][y][jc]

    const int b   = blockIdx.y;
    const int tid = threadIdx.x;

    // ---- decode tile: (level, x0, y0) from blockIdx.x in [0,85) ----
    int t = blockIdx.x;
    int x0, y0, base, W;
    float stride, bsize;
    if (t < 64)      { x0 = (t & 7) * 8;        y0 = (t >> 3) * 8;        base = 0;     W = 64; stride = 8.f;  bsize = 32.f;  }
    else if (t < 80) { int u = t - 64; x0 = (u & 3) * 8; y0 = (u >> 2) * 8; base = 36864; W = 32; stride = 16.f; bsize = 64.f;  }
    else if (t < 84) { int u = t - 80; x0 = (u & 1) * 8; y0 = (u >> 1) * 8; base = 46080; W = 16; stride = 32.f; bsize = 128.f; }
    else             { x0 = 0;                  y0 = 0;                    base = 48384; W = 8;  stride = 64.f; bsize = 256.f; }

    // ---- phase 1: boxes, areas, labels, keep-ballot ----
    if (tid < NM) {
        const float4 g = ((const float4*)(gt_boxes + (size_t)b * NM * 4))[tid];
        s_box[tid]  = g;
        s_area[tid] = (g.z - g.x) * (g.w - g.y);
        bool is64 = (gt_labels_raw[1] == 0) && (gt_labels_raw[3] == 0) &&
                    (gt_labels_raw[5] == 0);
        int idx = b * NM + tid;
        s_lab[tid] = is64 ? gt_labels_raw[2 * idx] : gt_labels_raw[idx];

        // conservative overlap window: anchor centers +/- max half-extent
        const float ext   = 1.123f * bsize;           // >= 0.5*2^(2/3)*sqrt(2)*bsize
        const float txmin = (x0 + 0.5f) * stride - ext;
        const float txmax = (x0 + 7.5f) * stride + ext;
        const float tymin = (y0 + 0.5f) * stride - ext;
        const float tymax = (y0 + 7.5f) * stride + ext;
        bool keep = (g.x < txmax) && (g.z > txmin) && (g.y < tymax) && (g.w > tymin);
        unsigned m = __ballot_sync(0xffffffffu, keep);
        if ((tid & 31) == 0) s_mask[tid >> 5] = m;
    }
    __syncthreads();

    // ---- phase 1b: stable compaction of kept boxes ----
    if (tid < NM) {
        unsigned m  = s_mask[tid >> 5];
        unsigned lt = (1u << (tid & 31)) - 1u;
        bool keep = (m >> (tid & 31)) & 1u;
        int pos = __popc(m & lt) + ((tid >= 32) ? __popc(s_mask[0]) : 0);
        if (keep) s_cidx[pos] = tid;
        if (tid == 0) s_nc = __popc(s_mask[0]) + __popc(s_mask[1]);
    }
    __syncthreads();

    const int nc  = s_nc;
    const int nc4 = (nc + 3) & ~3;

    // ---- phase 2a: rAS[jc][k] = 1/(area_a[k] + area_g[jc]) ----
    {
        const int jc = tid & 63;
        const int k  = tid >> 6;                 // 0..8
        if (jc < nc) {
            const int ks = k % 3;
            const float scl2 = (ks == 0) ? 1.0f
                             : (ks == 1) ? 1.5874010519681994f
                                         : 2.5198420997897464f;
            const float area_a = bsize * bsize * scl2;
            s_rAS[jc * NK + k] = 1.0f / (area_a + s_area[s_cidx[jc]]);
        }
    }
    __syncthreads();

    // ---- phase 2b: build IWn / IH tables for compacted boxes only ----
    {
        const int kx = tid >> 3;                 // 0..71 -> (k, x)
        const int j0 = tid & 7;
        const int k  = kx >> 3;
        const int x  = kx & 7;
        const int kr = k / 3, ks = k % 3;
        const float sr  = (kr == 0) ? 0.70710678118654752f
                        : (kr == 1) ? 1.0f : 1.41421356237309505f;
        const float scl = (ks == 0) ? 1.0f
                        : (ks == 1) ? 1.2599210498948732f : 1.5874010519681994f;
        const float hw  = 0.5f * bsize * scl * sr;
        const float hh  = 0.5f * bsize * scl / sr;
        const float cxx = (x0 + x + 0.5f) * stride;
        const float cyy = (y0 + x + 0.5f) * stride;  // x plays "y" for IH row
        float* __restrict__ wrow = s_IWn + kx * JP;
        float* __restrict__ hrow = s_IH  + kx * JP;

        for (int jc = j0; jc < nc4; jc += 8) {
            float wv = 0.f, hv = 0.f;
            if (jc < nc) {
                const float4 g = s_box[s_cidx[jc]];
                const float iw = fminf(cxx + hw, g.z) - fmaxf(cxx - hw, g.x);
                wv = fmaxf(iw, 0.f) * s_rAS[jc * NK + k];
                const float ih = fminf(cyy + hh, g.w) - fmaxf(cyy - hh, g.y);
                hv = fmaxf(ih, 0.f);
            }
            wrow[jc] = wv;
            hrow[jc] = hv;
        }
    }
    __syncthreads();

    // ---- main: argmax over compacted boxes of s = IWn*IH (monotone in IoU) ----
    const int k = tid >> 6;
    const int r = tid & 63;
    const int x = r & 7;
    const int y = r >> 3;

    const float* __restrict__ pw = s_IWn + (k * 8 + x) * JP;
    const float* __restrict__ ph = s_IH  + (k * 8 + y) * JP;

    float best_s = 0.0f;
    int   bc     = 0;
    #pragma unroll 2
    for (int j = 0; j < nc4; j += 4) {
        const float4 w = *(const float4*)(pw + j);
        const float4 h = *(const float4*)(ph + j);
        const float s0 = w.x * h.x;
        const float s1 = w.y * h.y;
        const float s2 = w.z * h.z;
        const float s3 = w.w * h.w;
        if (s0 > best_s) { best_s = s0; bc = j;     }
        if (s1 > best_s) { best_s = s1; bc = j + 1; }
        if (s2 > best_s) { best_s = s2; bc = j + 2; }
        if (s3 > best_s) { best_s = s3; bc = j + 3; }
    }
    // pruned boxes have score exactly 0; if everything is 0 the reference
    // argmax returns original j = 0.
    const int jorig = (best_s > 0.0f) ? s_cidx[bc] : 0;

    // ---- epilogue: exact IoU for winner, label, deltas ----
    const int kr = k / 3, ks = k % 3;
    const float sr  = (kr == 0) ? 0.70710678118654752f
                    : (kr == 1) ? 1.0f : 1.41421356237309505f;
    const float scl = (ks == 0) ? 1.0f
                    : (ks == 1) ? 1.2599210498948732f : 1.5874010519681994f;
    const float aw = bsize * scl * sr;
    const float ah = bsize * scl / sr;
    const float cx = (x0 + x + 0.5f) * stride;
    const float cy = (y0 + y + 0.5f) * stride;

    const float4 g = s_box[jorig];
    const float iw = fminf(cx + 0.5f * aw, g.z) - fmaxf(cx - 0.5f * aw, g.x);
    const float ih = fminf(cy + 0.5f * ah, g.w) - fmaxf(cy - 0.5f * ah, g.y);
    const float inter = fmaxf(iw, 0.0f) * fmaxf(ih, 0.0f);
    const float U = (aw * ah + s_area[jorig]) - inter;
    const float best = inter / U;                 // exact div for thresholds

    int lab = s_lab[jorig];
    if (best > 0.4f && best < 0.5f) lab = -1;
    if (best < 0.4f)                lab = 0;

    const float bw  = g.z - g.x;
    const float bh  = g.w - g.y;
    const float bcx = (g.x + g.z) * 0.5f;
    const float bcy = (g.y + g.w) * 0.5f;

    float4 d;
    d.x = __fdividef(bcx - cx, 0.1f * aw);
    d.y = __fdividef(bcy - cy, 0.1f * ah);
    d.z = __logf(__fdividef(bw, aw)) * 5.0f;
    d.w = __logf(__fdividef(bh, ah)) * 5.0f;

    const int a = base + (((y0 + y) * W + (x0 + x)) * NK + k);
    ((float4*)out)[(size_t)b * A_TOTAL + a] = d;
    out[(size_t)NB * A_TOTAL * 4 + (size_t)b * A_TOTAL + a] = (float)lab;
}

extern "C" void kernel_launch(void* const* d_in, const int* in_sizes, int n_in,
                              void* d_out, int out_size)
{
    // inputs: f3, f4, f5, f6 (unused: shapes static), gt_boxes, gt_labels
    const float* gt_boxes  = (const float*)d_in[4];
    const int*   gt_labels = (const int*)d_in[5];
    float*       out       = (float*)d_out;

    dim3 block(NTHREADS);
    dim3 grid(85, NB);   // 64+16+4+1 tiles per batch
    anchors_assign_kernel<<<grid, block>>>(gt_boxes, gt_labels, out);
}

// round 7
// speedup vs baseline: 5.2416x; 1.2078x over previous
#include <cuda_runtime.h>
#include <cuda_bf16.h>

#define NB 16          // batch
#define NM 64          // gt boxes per image
#define A_TOTAL 48960
#define NK 9
#define JP 68          // padded j-stride for tables (conflict-free float4 reads)
#define NTHREADS 576

__global__ __launch_bounds__(NTHREADS, 3)
void anchors_assign_kernel(const float* __restrict__ gt_boxes,
                           const int*   __restrict__ gt_labels_raw,
                           float*       __restrict__ out)
{
    __shared__ float4 s_box[NM];
    __shared__ int    s_lab[NM];
    __shared__ int    s_cidx[NM];          // compacted -> original j
    __shared__ int    s_nc;
    __shared__ __align__(16) float s_IWn[NK * 8 * JP];  // [k][x][jc]: clamp(IW)/AS
    __shared__ __align__(16) float s_IH [NK * 8 * JP];  // [k][y][jc]: clamp(IH)

    const int b   = blockIdx.y;
    const int tid = threadIdx.x;

    // ---- decode tile (heavy levels first): t = 84 - bx ----
    const int t = 84 - blockIdx.x;
    int x0, y0, base, W;
    float stride, bsize, rbsize;
    if (t < 64)      { x0 = (t & 7) * 8;        y0 = (t >> 3) * 8;        base = 0;     W = 64; stride = 8.f;  bsize = 32.f;  rbsize = 0.03125f;   }
    else if (t < 80) { int u = t - 64; x0 = (u & 3) * 8; y0 = (u >> 2) * 8; base = 36864; W = 32; stride = 16.f; bsize = 64.f;  rbsize = 0.015625f;  }
    else if (t < 84) { int u = t - 80; x0 = (u & 1) * 8; y0 = (u >> 1) * 8; base = 46080; W = 16; stride = 32.f; bsize = 128.f; rbsize = 0.0078125f; }
    else             { x0 = 0;                  y0 = 0;                    base = 48384; W = 8;  stride = 64.f; bsize = 256.f; rbsize = 0.00390625f;}

    // ---- phase 1 (warp 0 only): boxes, labels, ballot, stable compaction ----
    if (tid < 32) {
        const int lane = tid;
        const float4* gb = (const float4*)(gt_boxes + (size_t)b * NM * 4);
        const float4 g0 = gb[lane];
        const float4 g1 = gb[lane + 32];
        s_box[lane]      = g0;
        s_box[lane + 32] = g1;

        // dtype probe: labels in [1,21); int64 layout has zero high words.
        const bool is64 = (gt_labels_raw[1] == 0) && (gt_labels_raw[3] == 0) &&
                          (gt_labels_raw[5] == 0);
        const int i0 = b * NM + lane;
        s_lab[lane]      = is64 ? gt_labels_raw[2 * i0]        : gt_labels_raw[i0];
        s_lab[lane + 32] = is64 ? gt_labels_raw[2 * (i0 + 32)] : gt_labels_raw[i0 + 32];

        // conservative overlap window: anchor centers +/- max half-extent
        const float ext   = 1.123f * bsize;   // >= 0.5*2^(2/3)*sqrt(2)*bsize
        const float txmin = (x0 + 0.5f) * stride - ext;
        const float txmax = (x0 + 7.5f) * stride + ext;
        const float tymin = (y0 + 0.5f) * stride - ext;
        const float tymax = (y0 + 7.5f) * stride + ext;
        const bool k0 = (g0.x < txmax) && (g0.z > txmin) && (g0.y < tymax) && (g0.w > tymin);
        const bool k1 = (g1.x < txmax) && (g1.z > txmin) && (g1.y < tymax) && (g1.w > tymin);
        const unsigned m0 = __ballot_sync(0xffffffffu, k0);
        const unsigned m1 = __ballot_sync(0xffffffffu, k1);
        const unsigned lt = (1u << lane) - 1u;
        if (k0) s_cidx[__popc(m0 & lt)]               = lane;
        if (k1) s_cidx[__popc(m0) + __popc(m1 & lt)]  = lane + 32;
        if (lane == 0) s_nc = __popc(m0) + __popc(m1);
    }
    __syncthreads();                                   // barrier #1

    const int nc  = s_nc;
    const int nc4 = (nc + 3) & ~3;

    // ---- phase 2: build IWn (= clamp(IW)/AS) and IH tables, rcp inline ----
    {
        const int kx = tid >> 3;                 // 0..71 -> (k, x)
        const int j0 = tid & 7;
        const int k  = kx >> 3;
        const int x  = kx & 7;
        const int kr = k / 3, ks = k % 3;
        const float sr  = (kr == 0) ? 0.70710678118654752f
                        : (kr == 1) ? 1.0f : 1.41421356237309505f;
        const float scl = (ks == 0) ? 1.0f
                        : (ks == 1) ? 1.2599210498948732f : 1.5874010519681994f;
        const float hw  = 0.5f * bsize * scl * sr;
        const float hh  = 0.5f * bsize * scl / sr;
        const float cxx = (x0 + x + 0.5f) * stride;
        const float cyy = (y0 + x + 0.5f) * stride;  // x plays "y" for IH rows
        const float axlo = cxx - hw, axhi = cxx + hw;
        const float aylo = cyy - hh, ayhi = cyy + hh;
        const float area_a = 4.0f * hw * hh;
        float* __restrict__ wrow = s_IWn + kx * JP;
        float* __restrict__ hrow = s_IH  + kx * JP;

        for (int jc = j0; jc < nc4; jc += 8) {
            float wv = 0.f, hv = 0.f;
            if (jc < nc) {
                const float4 g  = s_box[s_cidx[jc]];
                const float iw  = fminf(axhi, g.z) - fmaxf(axlo, g.x);
                const float ih  = fminf(ayhi, g.w) - fmaxf(aylo, g.y);
                const float ag  = (g.z - g.x) * (g.w - g.y);
                const float rAS = __fdividef(1.0f, area_a + ag);
                wv = fmaxf(iw, 0.f) * rAS;
                hv = fmaxf(ih, 0.f);
            }
            wrow[jc] = wv;
            hrow[jc] = hv;
        }
    }
    __syncthreads();                                   // barrier #2

    // ---- main: packed-uint argmax of s = IWn*IH (monotone in IoU) ----
    // v = (bits(s) & ~63) | (63-jc); umax picks largest score, tie -> smallest jc.
    const int k = tid >> 6;
    const int r = tid & 63;
    const int x = r & 7;
    const int y = r >> 3;

    const float* __restrict__ pw = s_IWn + (k * 8 + x) * JP;
    const float* __restrict__ ph = s_IH  + (k * 8 + y) * JP;

    unsigned best = 63u;                // score 0, jc 0
    #pragma unroll 2
    for (int j = 0; j < nc4; j += 4) {
        const float4 w = *(const float4*)(pw + j);
        const float4 h = *(const float4*)(ph + j);
        const unsigned v0 = (__float_as_uint(w.x * h.x) & 0xFFFFFFC0u) | (unsigned)(63 - j);
        const unsigned v1 = (__float_as_uint(w.y * h.y) & 0xFFFFFFC0u) | (unsigned)(62 - j);
        const unsigned v2 = (__float_as_uint(w.z * h.z) & 0xFFFFFFC0u) | (unsigned)(61 - j);
        const unsigned v3 = (__float_as_uint(w.w * h.w) & 0xFFFFFFC0u) | (unsigned)(60 - j);
        best = max(best, max(max(v0, v1), max(v2, v3)));
    }
    const unsigned sbits = best & 0xFFFFFFC0u;
    const int jc    = 63 - (int)(best & 63u);
    const int jorig = sbits ? s_cidx[jc] : 0;   // all-zero IoU -> reference argmax = 0

    // ---- epilogue: exact inter/U for winner, thresholds via cross-compare ----
    const int kr = k / 3, ks = k % 3;
    const float sr      = (kr == 0) ? 0.70710678118654752f
                        : (kr == 1) ? 1.0f : 1.41421356237309505f;
    const float inv_sr  = (kr == 0) ? 1.41421356237309505f
                        : (kr == 1) ? 1.0f : 0.70710678118654752f;
    const float scl     = (ks == 0) ? 1.0f
                        : (ks == 1) ? 1.2599210498948732f : 1.5874010519681994f;
    const float inv_scl = (ks == 0) ? 1.0f
                        : (ks == 1) ? 0.79370052598409974f : 0.62996052494743658f;
    const float aw  = bsize * scl * sr;
    const float ah  = bsize * scl * inv_sr;
    const float raw = rbsize * inv_scl * inv_sr;   // 1/aw
    const float rah = rbsize * inv_scl * sr;       // 1/ah
    const float cx  = (x0 + x + 0.5f) * stride;
    const float cy  = (y0 + y + 0.5f) * stride;

    const float4 g = s_box[jorig];
    const float iw = fminf(cx + 0.5f * aw, g.z) - fmaxf(cx - 0.5f * aw, g.x);
    const float ih = fminf(cy + 0.5f * ah, g.w) - fmaxf(cy - 0.5f * ah, g.y);
    const float inter = fmaxf(iw, 0.0f) * fmaxf(ih, 0.0f);
    const float ag = (g.z - g.x) * (g.w - g.y);
    const float U  = (aw * ah + ag) - inter;

    int lab = s_lab[jorig];
    if (inter > 0.4f * U && inter < 0.5f * U) lab = -1;  // ignore band
    if (inter < 0.4f * U)                     lab = 0;   // background

    const float bw  = g.z - g.x;
    const float bh  = g.w - g.y;
    const float bcx = (g.x + g.z) * 0.5f;
    const float bcy = (g.y + g.w) * 0.5f;

    float4 d;
    d.x = (bcx - cx) * (10.0f * raw);
    d.y = (bcy - cy) * (10.0f * rah);
    d.z = __logf(bw * raw) * 5.0f;
    d.w = __logf(bh * rah) * 5.0f;

    const int a = base + (((y0 + y) * W + (x0 + x)) * NK + k);
    ((float4*)out)[(size_t)b * A_TOTAL + a] = d;
    out[(size_t)NB * A_TOTAL * 4 + (size_t)b * A_TOTAL + a] = (float)lab;
}

extern "C" void kernel_launch(void* const* d_in, const int* in_sizes, int n_in,
                              void* d_out, int out_size)
{
    // inputs: f3, f4, f5, f6 (unused: shapes static), gt_boxes, gt_labels
    const float* gt_boxes  = (const float*)d_in[4];
    const int*   gt_labels = (const int*)d_in[5];
    float*       out       = (float*)d_out;

    dim3 block(NTHREADS);
    dim3 grid(85, NB);   // 64+16+4+1 tiles per batch, heavy-first via t remap
    anchors_assign_kernel<<<grid, block>>>(gt_boxes, gt_labels, out);
}

// round 9
// speedup vs baseline: 5.2504x; 1.0017x over previous
#include <cuda_runtime.h>
#include <cuda_bf16.h>

#define NB 16          // batch
#define NM 64          // gt boxes per image
#define A_TOTAL 48960
#define NK 9
#define JP 68          // padded j-stride (272B rows: 16B-aligned, conflict-free)
#define NTHREADS 576

__global__ __launch_bounds__(NTHREADS, 3)
void anchors_assign_kernel(const float* __restrict__ gt_boxes,
                           const int*   __restrict__ gt_labels_raw,
                           float*       __restrict__ out)
{
    __shared__ float4 s_box[NM];
    __shared__ int    s_lab[NM];
    __shared__ int    s_cidx[NM];          // compacted -> original j
    __shared__ int    s_nc;
    __shared__ __align__(16) float s_IWn[8 * NK * JP];  // [x][k][jc]: clamp(IW)/AS
    __shared__ __align__(16) float s_IH [8 * NK * JP];  // [y][k][jc]: clamp(IH)

    const int b   = blockIdx.y;
    const int tid = threadIdx.x;

    // ---- decode tile (heavy levels first): t = 84 - bx ----
    const int t = 84 - blockIdx.x;
    int x0, y0, base, W;
    float stride, bsize, rbsize;
    if (t < 64)      { x0 = (t & 7) * 8;        y0 = (t >> 3) * 8;        base = 0;     W = 64; stride = 8.f;  bsize = 32.f;  rbsize = 0.03125f;   }
    else if (t < 80) { int u = t - 64; x0 = (u & 3) * 8; y0 = (u >> 2) * 8; base = 36864; W = 32; stride = 16.f; bsize = 64.f;  rbsize = 0.015625f;  }
    else if (t < 84) { int u = t - 80; x0 = (u & 1) * 8; y0 = (u >> 1) * 8; base = 46080; W = 16; stride = 32.f; bsize = 128.f; rbsize = 0.0078125f; }
    else             { x0 = 0;                  y0 = 0;                    base = 48384; W = 8;  stride = 64.f; bsize = 256.f; rbsize = 0.00390625f;}

    // ---- phase 1 (warp 0 only): boxes, labels, ballot, stable compaction ----
    if (tid < 32) {
        const int lane = tid;
        const float4* gb = (const float4*)(gt_boxes + (size_t)b * NM * 4);
        const float4 g0 = gb[lane];
        const float4 g1 = gb[lane + 32];
        s_box[lane]      = g0;
        s_box[lane + 32] = g1;

        // dtype probe: labels in [1,21); int64 layout has zero high words.
        const bool is64 = (gt_labels_raw[1] == 0) && (gt_labels_raw[3] == 0) &&
                          (gt_labels_raw[5] == 0);
        const int i0 = b * NM + lane;
        s_lab[lane]      = is64 ? gt_labels_raw[2 * i0]        : gt_labels_raw[i0];
        s_lab[lane + 32] = is64 ? gt_labels_raw[2 * (i0 + 32)] : gt_labels_raw[i0 + 32];

        // conservative overlap window: anchor centers +/- max half-extent
        const float ext   = 1.123f * bsize;   // >= 0.5*2^(2/3)*sqrt(2)*bsize
        const float txmin = (x0 + 0.5f) * stride - ext;
        const float txmax = (x0 + 7.5f) * stride + ext;
        const float tymin = (y0 + 0.5f) * stride - ext;
        const float tymax = (y0 + 7.5f) * stride + ext;
        const bool k0 = (g0.x < txmax) && (g0.z > txmin) && (g0.y < tymax) && (g0.w > tymin);
        const bool k1 = (g1.x < txmax) && (g1.z > txmin) && (g1.y < tymax) && (g1.w > tymin);
        const unsigned m0 = __ballot_sync(0xffffffffu, k0);
        const unsigned m1 = __ballot_sync(0xffffffffu, k1);
        const unsigned lt = (1u << lane) - 1u;
        if (k0) s_cidx[__popc(m0 & lt)]               = lane;
        if (k1) s_cidx[__popc(m0) + __popc(m1 & lt)]  = lane + 32;
        if (lane == 0) s_nc = __popc(m0) + __popc(m1);
    }
    __syncthreads();                                   // barrier #1

    const int nc  = s_nc;
    const int nc4 = (nc + 3) & ~3;

    // ---- phase 2: build IWn (= clamp(IW)/AS) and IH tables ----
    // row index r = x*9+k (IWn) / y*9+k (IH); build threads: r = tid>>3.
    {
        const int r  = tid >> 3;                 // 0..71
        const int j0 = tid & 7;
        const int k  = r % 9;
        const int x  = r / 9;                    // plays x for IWn, y for IH
        const int kr = k / 3, ks = k % 3;
        const float sr  = (kr == 0) ? 0.70710678118654752f
                        : (kr == 1) ? 1.0f : 1.41421356237309505f;
        const float scl = (ks == 0) ? 1.0f
                        : (ks == 1) ? 1.2599210498948732f : 1.5874010519681994f;
        const float hw  = 0.5f * bsize * scl * sr;
        const float hh  = 0.5f * bsize * scl / sr;
        const float cxx = (x0 + x + 0.5f) * stride;
        const float cyy = (y0 + x + 0.5f) * stride;
        const float axlo = cxx - hw, axhi = cxx + hw;
        const float aylo = cyy - hh, ayhi = cyy + hh;
        const float area_a = 4.0f * hw * hh;
        float* __restrict__ wrow = s_IWn + r * JP;
        float* __restrict__ hrow = s_IH  + r * JP;

        for (int jc = j0; jc < nc4; jc += 8) {
            float wv = 0.f, hv = 0.f;
            if (jc < nc) {
                const float4 g  = s_box[s_cidx[jc]];
                const float iw  = fminf(axhi, g.z) - fmaxf(axlo, g.x);
                const float ih  = fminf(ayhi, g.w) - fmaxf(aylo, g.y);
                const float ag  = (g.z - g.x) * (g.w - g.y);
                const float rAS = __fdividef(1.0f, area_a + ag);
                wv = fmaxf(iw, 0.f) * rAS;
                hv = fmaxf(ih, 0.f);
            }
            wrow[jc] = wv;
            hrow[jc] = hv;
        }
    }
    __syncthreads();                                   // barrier #2

    // ---- main: full-precision first-max argmax of s = IWn*IH ----
    // thread map: k fastest -> coalesced stores; rx = x*9+k, ry = y*9+k.
    const int k  = tid % 9;
    const int xy = tid / 9;
    const int x  = xy & 7;
    const int y  = xy >> 3;

    const float* __restrict__ pw = s_IWn + (x * 9 + k) * JP;
    const float* __restrict__ ph = s_IH  + (y * 9 + k) * JP;

    float best_s = 0.0f;
    int   bc     = 0;
    #pragma unroll 2
    for (int j = 0; j < nc4; j += 4) {
        const float4 w = *(const float4*)(pw + j);
        const float4 h = *(const float4*)(ph + j);
        const float s0 = w.x * h.x;
        const float s1 = w.y * h.y;
        const float s2 = w.z * h.z;
        const float s3 = w.w * h.w;
        if (s0 > best_s) { best_s = s0; bc = j;     }
        if (s1 > best_s) { best_s = s1; bc = j + 1; }
        if (s2 > best_s) { best_s = s2; bc = j + 2; }
        if (s3 > best_s) { best_s = s3; bc = j + 3; }
    }
    // pruned boxes score exactly 0; all-zero IoU -> reference argmax = 0.
    const int jorig = (best_s > 0.0f) ? s_cidx[bc] : 0;

    // ---- labels straight from s: iou = s/(1-s) monotone, so
    // iou < 0.4 <=> s < 2/7 ; iou < 0.5 <=> s < 1/3 ----
    int lab = s_lab[jorig];
    if (best_s > 0.28571428571428571f && best_s < 0.33333333333333333f) lab = -1;
    if (best_s < 0.28571428571428571f)                                  lab = 0;

    // ---- deltas vs matched box (reciprocals from constants) ----
    const int kr = k / 3, ks = k % 3;
    const float sr      = (kr == 0) ? 0.70710678118654752f
                        : (kr == 1) ? 1.0f : 1.41421356237309505f;
    const float inv_sr  = (kr == 0) ? 1.41421356237309505f
                        : (kr == 1) ? 1.0f : 0.70710678118654752f;
    const float inv_scl = (ks == 0) ? 1.0f
                        : (ks == 1) ? 0.79370052598409974f : 0.62996052494743658f;
    const float raw = rbsize * inv_scl * inv_sr;   // 1/aw
    const float rah = rbsize * inv_scl * sr;       // 1/ah
    const float cx  = (x0 + x + 0.5f) * stride;
    const float cy  = (y0 + y + 0.5f) * stride;

    const float4 g  = s_box[jorig];
    const float bw  = g.z - g.x;
    const float bh  = g.w - g.y;
    const float bcx = (g.x + g.z) * 0.5f;
    const float bcy = (g.y + g.w) * 0.5f;

    float4 d;
    d.x = (bcx - cx) * (10.0f * raw);
    d.y = (bcy - cy) * (10.0f * rah);
    d.z = __logf(bw * raw) * 5.0f;
    d.w = __logf(bh * rah) * 5.0f;

    // ---- stores: a is consecutive in tid (k fastest) -> coalesced ----
    const int a = base + (((y0 + y) * W + (x0 + x)) * NK + k);
    ((float4*)out)[(size_t)b * A_TOTAL + a] = d;
    out[(size_t)NB * A_TOTAL * 4 + (size_t)b * A_TOTAL + a] = (float)lab;
}

extern "C" void kernel_launch(void* const* d_in, const int* in_sizes, int n_in,
                              void* d_out, int out_size)
{
    // inputs: f3, f4, f5, f6 (unused: shapes static), gt_boxes, gt_labels
    const float* gt_boxes  = (const float*)d_in[4];
    const int*   gt_labels = (const int*)d_in[5];
    float*       out       = (float*)d_out;

    dim3 block(NTHREADS);
    dim3 grid(85, NB);   // 64+16+4+1 tiles per batch, heavy-first via t remap
    anchors_assign_kernel<<<grid, block>>>(gt_boxes, gt_labels, out);
}